// round 15
// baseline (speedup 1.0000x reference)
#include <cuda_runtime.h>
#include <cstdint>
#include <math.h>

#define BB 64
#define PP 16320
#define OO 24
#define CC 81
#define WCH 8                 // rows per chunk (per-warp)
#define WNC 5                 // chunks per warp -> 40 rows/warp
#define CHF (WCH*CC)          // 648 floats per chunk
#define CHF4 (CHF/4)          // 162 float4 per chunk
#define THLOG (-4.5951199f)   // log(0.01/0.99)
#define NBIN 4096             // coarse histogram bins (v >> 19)

// ---------------- device scratch (self-resetting across replays) ----------------
__device__ double g_loss_l;                          // reset by k_topk finalize
__device__ double g_loss_c;
__device__ int    g_pos_count[BB];
__device__ int    g_done;
__device__ unsigned long long g_best_prior[BB * OO]; // re-armed by k_topk
__device__ float  g_ce_mine[(size_t)BB * PP];        // fully overwritten each run

__device__ __forceinline__ void cp16(void* smem, const void* gmem) {
    unsigned sa = (unsigned)__cvta_generic_to_shared(smem);
    asm volatile("cp.async.cg.shared.global [%0], [%1], 16;\n" :: "r"(sa), "l"(gmem));
}

// decode ARM box -> xyxy + area (shared by all kernels; must match bitwise)
__device__ __forceinline__ void decode4(float4 pr, float4 al,
    float& dx1, float& dy1, float& dx2, float& dy2, float& area) {
    float cx = pr.x + al.x * 0.1f * pr.z;
    float cy = pr.y + al.y * 0.1f * pr.w;
    float wd = pr.z * __expf(al.z * 0.2f);
    float ht = pr.w * __expf(al.w * 0.2f);
    dx1 = cx - wd * 0.5f; dy1 = cy - ht * 0.5f;
    dx2 = cx + wd * 0.5f; dy2 = cy + ht * 0.5f;
    area = (dx2 - dx1) * (dy2 - dy1);
}

// smooth-L1 positive loc loss (shared; must match bitwise)
__device__ __forceinline__ float pos_loss(float4 pr, float4 al, float4 t, float4 ol) {
    float cx = pr.x + al.x * 0.1f * pr.z;
    float cy = pr.y + al.y * 0.1f * pr.w;
    float wd = pr.z * __expf(al.z * 0.2f);
    float ht = pr.w * __expf(al.w * 0.2f);
    float x1 = cx - wd * 0.5f, y1 = cy - ht * 0.5f;
    float x2 = cx + wd * 0.5f, y2 = cy + ht * 0.5f;
    float dcx = (x1 + x2) * 0.5f, dcy = (y1 + y2) * 0.5f;
    float dw = x2 - x1, dh = y2 - y1;
    float gcx = ((t.x + t.z) * 0.5f - dcx) / (0.1f * dw);
    float gcy = ((t.y + t.w) * 0.5f - dcy) / (0.1f * dh);
    float gw  = __logf((t.z - t.x) / dw) / 0.2f;
    float gh  = __logf((t.w - t.y) / dh) / 0.2f;
    float d0 = fabsf(ol.x - gcx), d1 = fabsf(ol.y - gcy);
    float d2 = fabsf(ol.z - gw),  d3 = fabsf(ol.w - gh);
    return (d0 < 1.f ? 0.5f * d0 * d0 : d0 - 0.5f)
         + (d1 < 1.f ? 0.5f * d1 * d1 : d1 - 0.5f)
         + (d2 < 1.f ? 0.5f * d2 * d2 : d2 - 0.5f)
         + (d3 < 1.f ? 0.5f * d3 * d3 : d3 - 0.5f);
}

// quad-split best-object for one prior: quad member q covers objects q*6..q*6+5.
__device__ __forceinline__ void best6(const float4* s_gt, const float* s_at, int q,
    float dx1, float dy1, float dx2, float dy2, float area_d,
    float& bI, float& bD, int& bo) {
    bI = 0.f; bD = 1.f; bo = q * 6;
    #pragma unroll
    for (int j = 0; j < 6; j++) {
        int o = q * 6 + j;
        float4 t = s_gt[o];
        float lx = fmaxf(t.x, dx1), ly = fmaxf(t.y, dy1);
        float rx = fminf(t.z, dx2), ry = fminf(t.w, dy2);
        float iw = fmaxf(rx - lx, 0.f), ih = fmaxf(ry - ly, 0.f);
        float I = iw * ih;
        float D = s_at[o] + area_d - I;
        if (I * bD > bI * D) { bI = I; bD = D; bo = o; }   // smallest o on ties
    }
}

// ---------------- kernel A (side stream): per-object global best prior ----------------
__global__ void __launch_bounds__(128)
k_match(const float* __restrict__ arm_loc,
        const float* __restrict__ priors,
        const float* __restrict__ gt_boxes) {
    int b = blockIdx.y;
    int tid = threadIdx.x;
    int w = tid >> 5, lane = tid & 31;
    int p = blockIdx.x * 128 + tid;

    __shared__ float4 s_gt[OO];
    __shared__ float  s_at[OO];
    __shared__ float  s_I[4][32][25];   // pad 25 -> conflict-free
    __shared__ float  s_D[4][32][25];
    if (tid < OO) {
        float4 t = ((const float4*)gt_boxes)[b * OO + tid];
        s_gt[tid] = t;
        s_at[tid] = (t.z - t.x) * (t.w - t.y);
    }
    __syncthreads();

    bool valid = (p < PP);
    float dx1 = 0.f, dy1 = 0.f, dx2 = 0.f, dy2 = 0.f, area_d = 0.f;
    if (valid) {
        float4 pr = ((const float4*)priors)[p];
        float4 lc = ((const float4*)arm_loc)[(size_t)b * PP + p];
        decode4(pr, lc, dx1, dy1, dx2, dy2, area_d);
    }

    #pragma unroll 6
    for (int o = 0; o < OO; o++) {
        float I = 0.f, D = 1.f;
        if (valid) {
            float4 t = s_gt[o];
            float lx = fmaxf(t.x, dx1), ly = fmaxf(t.y, dy1);
            float rx = fminf(t.z, dx2), ry = fminf(t.w, dy2);
            float iw = fmaxf(rx - lx, 0.f), ih = fmaxf(ry - ly, 0.f);
            I = iw * ih;
            D = s_at[o] + area_d - I;
        }
        s_I[w][lane][o] = I;
        s_D[w][lane][o] = D;
    }
    __syncwarp();

    if (lane < OO) {
        float wI = s_I[w][0][lane], wD = s_D[w][0][lane]; int wj = 0;
        #pragma unroll 8
        for (int j = 1; j < 32; j++) {
            float I = s_I[w][j][lane], D = s_D[w][j][lane];
            if (I * wD > wI * D) { wI = I; wD = D; wj = j; }
        }
        if (wI > 0.f) {
            float iou = wI / wD;
            unsigned pw = (unsigned)(blockIdx.x * 128 + w * 32 + wj);
            unsigned long long cand =
                (((unsigned long long)__float_as_uint(iou)) << 32) |
                (unsigned long long)(0xFFFFFFFFu - pw);
            atomicMax(&g_best_prior[b * OO + lane], cand);
        }
    }
}

// ---------------- kernel B (main stream): CE + per-row match + positive losses ----------
__global__ void __launch_bounds__(256)
k_main(const float* __restrict__ arm_loc,
       const float* __restrict__ arm_conf,
       const float* __restrict__ odm_loc,
       const float* __restrict__ odm_conf,
       const float* __restrict__ priors,
       const float* __restrict__ gt_boxes,
       const int*   __restrict__ gt_labels) {
    extern __shared__ float sh[];            // 8 warps * 4 slots * 648 floats = 82944 B
    __shared__ float4 s_gt[OO];
    __shared__ float  s_at[OO];
    __shared__ int    s_lab[OO];

    int b = blockIdx.y;
    int tid = threadIdx.x;
    int w = tid >> 5, lane = tid & 31;
    int warpg = blockIdx.x * 8 + w;          // 0..407
    int row0 = warpg * (WCH * WNC);
    size_t bbase = (size_t)b * PP;
    const float* confb = odm_conf + bbase * CC;
    float* ws = sh + w * (4 * CHF);

    #pragma unroll
    for (int c = 0; c < 3; c++) {
        const float4* src = (const float4*)(confb + (size_t)(row0 + c * WCH) * CC);
        float* dst = ws + c * CHF;
        #pragma unroll
        for (int t = 0; t < 6; t++) {
            int i = lane + t * 32;
            if (i < CHF4) cp16(dst + i * 4, src + i);
        }
        asm volatile("cp.async.commit_group;\n" ::);
    }

    if (tid < OO) {
        float4 t = ((const float4*)gt_boxes)[b * OO + tid];
        s_gt[tid] = t;
        s_at[tid] = (t.z - t.x) * (t.w - t.y);
        s_lab[tid] = gt_labels[b * OO + tid];
    }
    __syncthreads();                          // only block barrier

    int r = lane >> 2, q = lane & 3;          // 8 rows x 4 lanes per row

    #pragma unroll
    for (int c = 0; c < WNC; c++) {
        if (c + 3 < WNC) {
            const float4* src = (const float4*)(confb + (size_t)(row0 + (c + 3) * WCH) * CC);
            float* dst = ws + ((c + 3) & 3) * CHF;
            #pragma unroll
            for (int t = 0; t < 6; t++) {
                int i = lane + t * 32;
                if (i < CHF4) cp16(dst + i * 4, src + i);
            }
            asm volatile("cp.async.commit_group;\n" ::);
        }

        int p0 = row0 + c * WCH;
        int prow = p0 + r;
        size_t idx = bbase + prow;

        float4 pr = ((const float4*)priors)[prow];
        float4 al = ((const float4*)arm_loc)[idx];
        float dx1, dy1, dx2, dy2, area_d;
        decode4(pr, al, dx1, dy1, dx2, dy2, area_d);
        float bI, bD; int bo;
        best6(s_gt, s_at, q, dx1, dy1, dx2, dy2, area_d, bI, bD, bo);
        #pragma unroll
        for (int s = 1; s <= 2; s <<= 1) {
            float oI = __shfl_xor_sync(0xFFFFFFFFu, bI, s);
            float oD = __shfl_xor_sync(0xFFFFFFFFu, bD, s);
            int  obo = __shfl_xor_sync(0xFFFFFFFFu, bo, s);
            float L = oI * bD, R = bI * oD;
            if (L > R || (L == R && obo < bo)) { bI = oI; bD = oD; bo = obo; }
        }
        bool flag = (2.f * bI >= bD);

        if (c < 2)       asm volatile("cp.async.wait_group 3;\n" ::);
        else if (c == 2) asm volatile("cp.async.wait_group 2;\n" ::);
        else if (c == 3) asm volatile("cp.async.wait_group 1;\n" ::);
        else             asm volatile("cp.async.wait_group 0;\n" ::);
        __syncwarp();

        const float* s = ws + (c & 3) * CHF;
        const float* rp = s + r * CC + q * 20;
        float a0 = 0.f, a1 = 0.f;
        #pragma unroll
        for (int j = 0; j < 20; j += 2) {
            a0 += __expf(rp[j]);
            a1 += __expf(rp[j + 1]);
        }
        float e = a0 + a1;
        if (q == 0) e += __expf(s[r * CC + 80]);
        e += __shfl_xor_sync(0xFFFFFFFFu, e, 1);
        e += __shfl_xor_sync(0xFFFFFFFFu, e, 2);

        if (q == 0) {
            float lse = __logf(e);
            int conf_t = flag ? s_lab[bo] : 0;
            float ce = lse - s[r * CC + conf_t];

            float2 ac = ((const float2*)arm_conf)[idx];
            bool pos = (conf_t > 0) && ((ac.y - ac.x) > THLOG);

            g_ce_mine[idx] = pos ? 0.f : ce;

            if (pos) {
                float4 ol = ((const float4*)odm_loc)[idx];
                float sl = pos_loss(pr, al, s_gt[bo], ol);
                atomicAdd(&g_loss_l, (double)sl);
                atomicAdd(&g_loss_c, (double)ce);
                atomicAdd(&g_pos_count[b], 1);
            }
        }
        __syncwarp();
    }
}

// ---------------- kernel C: forced-positive fixup (after A and B) ----------------
__global__ void __launch_bounds__(32)
k_fix(const float* __restrict__ arm_loc,
      const float* __restrict__ arm_conf,
      const float* __restrict__ odm_loc,
      const float* __restrict__ odm_conf,
      const float* __restrict__ priors,
      const float* __restrict__ gt_boxes,
      const int*   __restrict__ gt_labels) {
    int b = blockIdx.x;
    int o = threadIdx.x;

    int p;
    if (o < OO) {
        unsigned long long fc = g_best_prior[b * OO + o];
        p = (fc >> 32) ? (int)(0xFFFFFFFFu - (unsigned)(fc & 0xFFFFFFFFu)) : 0;
    } else {
        p = 0x40000000 + o;
    }
    unsigned mm = __match_any_sync(0xFFFFFFFFu, p);
    bool winner = (o < OO) && ((31 - __clz((int)mm)) == o);
    if (!winner) return;

    size_t idx = (size_t)b * PP + p;
    const float* row = odm_conf + idx * CC;

    float eq[4];
    #pragma unroll
    for (int qq = 0; qq < 4; qq++) {
        float a0 = 0.f, a1 = 0.f;
        #pragma unroll
        for (int j = 0; j < 20; j += 2) {
            a0 += __expf(row[qq * 20 + j]);
            a1 += __expf(row[qq * 20 + j + 1]);
        }
        eq[qq] = a0 + a1;
    }
    eq[0] += __expf(row[80]);
    float lse = __logf((eq[0] + eq[1]) + (eq[2] + eq[3]));

    float4 pr = ((const float4*)priors)[p];
    float4 al = ((const float4*)arm_loc)[idx];
    float dx1, dy1, dx2, dy2, area_d;
    decode4(pr, al, dx1, dy1, dx2, dy2, area_d);
    float4 gtl[OO]; float atl[OO];
    for (int o2 = 0; o2 < OO; o2++) {
        gtl[o2] = ((const float4*)gt_boxes)[b * OO + o2];
        atl[o2] = (gtl[o2].z - gtl[o2].x) * (gtl[o2].w - gtl[o2].y);
    }
    float qI[4], qD[4]; int qO[4];
    #pragma unroll
    for (int qq = 0; qq < 4; qq++)
        best6(gtl, atl, qq, dx1, dy1, dx2, dy2, area_d, qI[qq], qD[qq], qO[qq]);
    #pragma unroll
    for (int s = 1; s <= 2; s <<= 1) {
        #pragma unroll
        for (int qq = 0; qq < 4; qq++) {
            int pp = qq ^ s;
            if (pp > qq) {
                float L1 = qI[pp] * qD[qq], R1 = qI[qq] * qD[pp];
                float nI, nD; int nO;
                if (L1 > R1 || (L1 == R1 && qO[pp] < qO[qq]))
                     { nI = qI[pp]; nD = qD[pp]; nO = qO[pp]; }
                else { nI = qI[qq]; nD = qD[qq]; nO = qO[qq]; }
                qI[qq] = nI; qD[qq] = nD; qO[qq] = nO;
                qI[pp] = nI; qD[pp] = nD; qO[pp] = nO;
            }
        }
    }
    float bI = qI[0], bD = qD[0]; int bo = qO[0];
    bool flag = (2.f * bI >= bD);

    int conf_t_old = flag ? gt_labels[b * OO + bo] : 0;
    float ce_old = lse - row[conf_t_old];
    float2 ac = ((const float2*)arm_conf)[idx];
    bool score_ok = (ac.y - ac.x) > THLOG;
    bool pos_old = (conf_t_old > 0) && score_ok;

    int conf_t_new = gt_labels[b * OO + o];
    float ce_new = lse - row[conf_t_new];
    bool pos_new = score_ok;

    g_ce_mine[idx] = pos_new ? 0.f : ce_new;

    double dLc = 0.0, dLl = 0.0; int dN = 0;
    if (pos_old || pos_new) {
        float4 ol = ((const float4*)odm_loc)[idx];
        if (pos_old) {
            dLc -= (double)ce_old; dN -= 1;
            dLl -= (double)pos_loss(pr, al, gtl[bo], ol);
        }
        if (pos_new) {
            dLc += (double)ce_new; dN += 1;
            dLl += (double)pos_loss(pr, al, gtl[o], ol);
        }
    }
    if (dLc != 0.0) atomicAdd(&g_loss_c, dLc);
    if (dLl != 0.0) atomicAdd(&g_loss_l, dLl);
    if (dN)         atomicAdd(&g_pos_count[b], dN);
}

// ---------------- kernel D: top-k via coarse histogram prune + finalize ----------------
// dyn smem: 4096 double sums (32768) + 4096 int counts (16384) + PP uint list (65280)
__global__ void __launch_bounds__(1024) k_topk(float* __restrict__ out) {
    int b = blockIdx.x;
    extern __shared__ char dsm[];
    double*   s_bsum = (double*)dsm;                       // [NBIN]
    int*      s_bcnt = (int*)(dsm + NBIN * 8);             // [NBIN]
    unsigned* s_list = (unsigned*)(dsm + NBIN * 12);       // [PP]

    __shared__ int    s_wc[32];
    __shared__ double s_ws[32];
    __shared__ int    s_B, s_ca, s_nl, s_rem, s_cgt, s_last;
    __shared__ unsigned s_pref;
    __shared__ double s_sa, s_sum;

    int t = threadIdx.x;
    int warp = t >> 5, lane = t & 31;

    if (t < OO) g_best_prior[b * OO + t] = 0x00000000FFFFFFFFull;  // next replay

    // zero histogram
    #pragma unroll
    for (int i = 0; i < NBIN / 1024; i++) {
        s_bcnt[t + i * 1024] = 0;
        s_bsum[t + i * 1024] = 0.0;
    }
    if (t == 0) { s_nl = 0; s_sum = 0.0; s_cgt = 0; }
    __syncthreads();

    int np = g_pos_count[b];
    int k = 3 * np; if (k > PP - 1) k = PP - 1;

    if (k > 0) {
        // ---- pass A: coarse (count, sum) histogram on top-13 bits ----
        for (int i = t; i < PP; i += 1024) {
            float f = g_ce_mine[(size_t)b * PP + i];
            unsigned v = __float_as_uint(f);
            int bin = v >> 19;
            atomicAdd(&s_bcnt[bin], 1);
            atomicAdd(&s_bsum[bin], (double)f);
        }
        __syncthreads();

        // ---- suffix scan from top to locate crossing bin B ----
        int pc = 0; double ps = 0.0;
        #pragma unroll
        for (int j = 0; j < 4; j++) {
            pc += s_bcnt[t * 4 + j];
            ps += s_bsum[t * 4 + j];
        }
        int sc = pc; double ss = ps;                 // inclusive suffix within warp
        #pragma unroll
        for (int sh = 1; sh < 32; sh <<= 1) {
            int oc = __shfl_down_sync(0xFFFFFFFFu, sc, sh);
            double os = __shfl_down_sync(0xFFFFFFFFu, ss, sh);
            if (lane + sh < 32) { sc += oc; ss += os; }
        }
        if (lane == 0) { s_wc[warp] = sc; s_ws[warp] = ss; }
        __syncthreads();
        int aw = 0; double aws = 0.0;                // totals of warps above
        for (int w2 = warp + 1; w2 < 32; w2++) { aw += s_wc[w2]; aws += s_ws[w2]; }
        int above = aw + (sc - pc);                  // lanes strictly above in warp
        double aboves = aws + (ss - ps);
        {
            int run = above; double runs = aboves;
            #pragma unroll
            for (int j = 3; j >= 0; j--) {
                int bin = t * 4 + j;
                int c = s_bcnt[bin];
                if (run < k && k <= run + c) {       // exactly one (t,j) true
                    s_B = bin; s_ca = run; s_sa = runs;
                }
                run += c; runs += s_bsum[bin];
            }
        }
        __syncthreads();
        int B = s_B, k2 = k - s_ca;

        // ---- pass B: gather bin-B elements ----
        for (int i = t; i < PP; i += 1024) {
            unsigned v = __float_as_uint(g_ce_mine[(size_t)b * PP + i]);
            if ((int)(v >> 19) == B)
                s_list[atomicAdd(&s_nl, 1)] = v;
        }
        __syncthreads();
        int n = s_nl;
        int npad = (n + 1023) & ~1023;

        // ---- byte-radix select of k2-th largest within the small list ----
        int rem = k2;
        unsigned pref = 0;
        #pragma unroll
        for (int d = 24; d >= 0; d -= 8) {
            if (t < 256) s_bcnt[t] = 0;              // reuse as 256-bin hist
            __syncthreads();
            unsigned pmask = (d == 24) ? 0u : (0xFFFFFFFFu << (d + 8));
            for (int i = t; i < npad; i += 1024) {   // uniform trips
                bool part = false; unsigned bin = 0;
                if (i < n) {
                    unsigned v = s_list[i];
                    part = ((v & pmask) == pref);
                    bin = (v >> d) & 0xFFu;
                }
                unsigned act = __ballot_sync(0xFFFFFFFFu, part);
                if (part) {
                    unsigned same = __match_any_sync(act, bin);
                    if ((__ffs(same) - 1) == lane)
                        atomicAdd(&s_bcnt[bin], __popc(same));
                }
            }
            __syncthreads();
            if (t < 32) {
                int loc[8]; int s8 = 0;
                #pragma unroll
                for (int j = 0; j < 8; j++) { loc[j] = s_bcnt[t * 8 + j]; s8 += loc[j]; }
                int suf = s8;
                #pragma unroll
                for (int sh = 1; sh < 32; sh <<= 1) {
                    int oo = __shfl_down_sync(0xFFFFFFFFu, suf, sh);
                    if (t + sh < 32) suf += oo;
                }
                int abv = suf - s8;
                int cand = -1, candgt = 0;
                int run = abv;
                #pragma unroll
                for (int j = 7; j >= 0; j--) {
                    int gt = run;
                    run += loc[j];
                    if (cand < 0 && run >= rem) { cand = t * 8 + j; candgt = gt; }
                }
                int wm = __reduce_max_sync(0xFFFFFFFFu, (unsigned)(cand + 1)) - 1;
                if (cand == wm && cand >= 0) {
                    s_rem = rem - candgt;
                    s_pref = pref | ((unsigned)cand << d);
                }
            }
            __syncthreads();
            rem = s_rem;
            pref = s_pref;
            __syncthreads();
        }
        unsigned lo = pref;                          // k-th largest value bits

        // strictly-greater sum within list + tie fill
        double sum = 0.0; int cgt = 0;
        for (int i = t; i < n; i += 1024) {
            unsigned v = s_list[i];
            if (v > lo) { sum += (double)__uint_as_float(v); cgt++; }
        }
        #pragma unroll
        for (int s = 16; s > 0; s >>= 1) {
            sum += __shfl_xor_sync(0xFFFFFFFFu, sum, s);
            cgt += __shfl_xor_sync(0xFFFFFFFFu, cgt, s);
        }
        if (lane == 0) { atomicAdd(&s_sum, sum); atomicAdd(&s_cgt, cgt); }
        __syncthreads();
        if (t == 0) {
            double S = s_sa + s_sum +
                       (double)(k2 - s_cgt) * (double)__uint_as_float(lo);
            atomicAdd(&g_loss_c, S);
        }
    }

    // ---- arrival + finalize by last block ----
    __threadfence();
    if (t == 0) s_last = (atomicAdd(&g_done, 1) == BB - 1);
    __syncthreads();
    if (s_last) {
        int* ib = (int*)s_list;
        if (t < BB) { ib[t] = g_pos_count[t]; g_pos_count[t] = 0; }
        __syncthreads();
        if (t == 0) {
            int N = 0;
            for (int i = 0; i < BB; i++) N += ib[i];
            double lc = atomicAdd(&g_loss_c, 0.0);
            double ll = g_loss_l;
            out[0] = (float)(ll / (double)N);
            out[1] = (float)(lc / (double)N);
            g_loss_l = 0.0; g_loss_c = 0.0; g_done = 0;
        }
    }
}

// ---------------- launch: fork k_match onto a side stream ----------------
extern "C" void kernel_launch(void* const* d_in, const int* in_sizes, int n_in,
                              void* d_out, int out_size) {
    const float* arm_loc  = (const float*)d_in[0];
    const float* arm_conf = (const float*)d_in[1];
    const float* odm_loc  = (const float*)d_in[2];
    const float* odm_conf = (const float*)d_in[3];
    const float* priors   = (const float*)d_in[4];
    const float* gt_boxes = (const float*)d_in[5];
    const int*   gt_labels= (const int*)  d_in[6];
    float* out = (float*)d_out;

    int kmain_smem = 8 * 4 * CHF * (int)sizeof(float);       // 82944 B
    int ktopk_smem = NBIN * 12 + PP * (int)sizeof(unsigned); // 114432 B

    static cudaStream_t s2 = nullptr;
    static cudaEvent_t ev1 = nullptr, ev2 = nullptr;
    static bool inited = false;
    if (!inited) {
        cudaStreamCreateWithFlags(&s2, cudaStreamNonBlocking);
        cudaEventCreateWithFlags(&ev1, cudaEventDisableTiming);
        cudaEventCreateWithFlags(&ev2, cudaEventDisableTiming);
        cudaFuncSetAttribute(k_main, cudaFuncAttributeMaxDynamicSharedMemorySize,
                             kmain_smem);
        cudaFuncSetAttribute(k_topk, cudaFuncAttributeMaxDynamicSharedMemorySize,
                             ktopk_smem);
        inited = true;
    }

    // fork: k_match on s2, concurrent with k_main on the main stream
    cudaEventRecord(ev1, 0);
    cudaStreamWaitEvent(s2, ev1, 0);
    {
        dim3 g(128, BB);
        k_match<<<g, 128, 0, s2>>>(arm_loc, priors, gt_boxes);
    }
    cudaEventRecord(ev2, s2);
    {
        dim3 g(51, BB);
        k_main<<<g, 256, kmain_smem>>>(arm_loc, arm_conf, odm_loc, odm_conf,
                                       priors, gt_boxes, gt_labels);
    }
    // join: k_fix needs both k_match (g_best_prior) and k_main (losses/ce_mine)
    cudaStreamWaitEvent(0, ev2, 0);
    k_fix<<<BB, 32>>>(arm_loc, arm_conf, odm_loc, odm_conf,
                      priors, gt_boxes, gt_labels);
    k_topk<<<BB, 1024, ktopk_smem>>>(out);
}

// round 17
// speedup vs baseline: 2.8439x; 2.8439x over previous
#include <cuda_runtime.h>
#include <cstdint>
#include <math.h>

#define BB 64
#define PP 16320
#define OO 24
#define CC 81
#define WCH 8                 // rows per chunk (per-warp)
#define WNC 5                 // chunks per warp -> 40 rows/warp
#define CHF (WCH*CC)          // 648 floats per chunk
#define CHF4 (CHF/4)          // 162 float4 per chunk
#define THLOG (-4.5951199f)   // log(0.01/0.99)
#define NBIN 4096             // coarse histogram bins (v >> 19)

// ---------------- device scratch (self-resetting across replays) ----------------
__device__ double g_loss_l;                          // reset by k_topk finalize
__device__ double g_loss_c;
__device__ int    g_pos_count[BB];
__device__ int    g_done;
__device__ unsigned long long g_best_prior[BB * OO]; // re-armed by k_topk
__device__ float  g_ce_mine[(size_t)BB * PP];        // fully overwritten each run

__device__ __forceinline__ void cp16(void* smem, const void* gmem) {
    unsigned sa = (unsigned)__cvta_generic_to_shared(smem);
    asm volatile("cp.async.cg.shared.global [%0], [%1], 16;\n" :: "r"(sa), "l"(gmem));
}

// decode ARM box -> xyxy + area (shared by all kernels; must match bitwise)
__device__ __forceinline__ void decode4(float4 pr, float4 al,
    float& dx1, float& dy1, float& dx2, float& dy2, float& area) {
    float cx = pr.x + al.x * 0.1f * pr.z;
    float cy = pr.y + al.y * 0.1f * pr.w;
    float wd = pr.z * __expf(al.z * 0.2f);
    float ht = pr.w * __expf(al.w * 0.2f);
    dx1 = cx - wd * 0.5f; dy1 = cy - ht * 0.5f;
    dx2 = cx + wd * 0.5f; dy2 = cy + ht * 0.5f;
    area = (dx2 - dx1) * (dy2 - dy1);
}

// smooth-L1 positive loc loss (shared; must match bitwise)
__device__ __forceinline__ float pos_loss(float4 pr, float4 al, float4 t, float4 ol) {
    float cx = pr.x + al.x * 0.1f * pr.z;
    float cy = pr.y + al.y * 0.1f * pr.w;
    float wd = pr.z * __expf(al.z * 0.2f);
    float ht = pr.w * __expf(al.w * 0.2f);
    float x1 = cx - wd * 0.5f, y1 = cy - ht * 0.5f;
    float x2 = cx + wd * 0.5f, y2 = cy + ht * 0.5f;
    float dcx = (x1 + x2) * 0.5f, dcy = (y1 + y2) * 0.5f;
    float dw = x2 - x1, dh = y2 - y1;
    float gcx = ((t.x + t.z) * 0.5f - dcx) / (0.1f * dw);
    float gcy = ((t.y + t.w) * 0.5f - dcy) / (0.1f * dh);
    float gw  = __logf((t.z - t.x) / dw) / 0.2f;
    float gh  = __logf((t.w - t.y) / dh) / 0.2f;
    float d0 = fabsf(ol.x - gcx), d1 = fabsf(ol.y - gcy);
    float d2 = fabsf(ol.z - gw),  d3 = fabsf(ol.w - gh);
    return (d0 < 1.f ? 0.5f * d0 * d0 : d0 - 0.5f)
         + (d1 < 1.f ? 0.5f * d1 * d1 : d1 - 0.5f)
         + (d2 < 1.f ? 0.5f * d2 * d2 : d2 - 0.5f)
         + (d3 < 1.f ? 0.5f * d3 * d3 : d3 - 0.5f);
}

// quad-split best-object for one prior: quad member q covers objects q*6..q*6+5.
__device__ __forceinline__ void best6(const float4* s_gt, const float* s_at, int q,
    float dx1, float dy1, float dx2, float dy2, float area_d,
    float& bI, float& bD, int& bo) {
    bI = 0.f; bD = 1.f; bo = q * 6;
    #pragma unroll
    for (int j = 0; j < 6; j++) {
        int o = q * 6 + j;
        float4 t = s_gt[o];
        float lx = fmaxf(t.x, dx1), ly = fmaxf(t.y, dy1);
        float rx = fminf(t.z, dx2), ry = fminf(t.w, dy2);
        float iw = fmaxf(rx - lx, 0.f), ih = fmaxf(ry - ly, 0.f);
        float I = iw * ih;
        float D = s_at[o] + area_d - I;
        if (I * bD > bI * D) { bI = I; bD = D; bo = o; }   // smallest o on ties
    }
}

// ---------------- kernel A (side stream): per-object global best prior ----------------
__global__ void __launch_bounds__(128)
k_match(const float* __restrict__ arm_loc,
        const float* __restrict__ priors,
        const float* __restrict__ gt_boxes) {
    int b = blockIdx.y;
    int tid = threadIdx.x;
    int w = tid >> 5, lane = tid & 31;
    int p = blockIdx.x * 128 + tid;

    __shared__ float4 s_gt[OO];
    __shared__ float  s_at[OO];
    __shared__ float  s_I[4][32][25];   // pad 25 -> conflict-free
    __shared__ float  s_D[4][32][25];
    if (tid < OO) {
        float4 t = ((const float4*)gt_boxes)[b * OO + tid];
        s_gt[tid] = t;
        s_at[tid] = (t.z - t.x) * (t.w - t.y);
    }
    __syncthreads();

    bool valid = (p < PP);
    float dx1 = 0.f, dy1 = 0.f, dx2 = 0.f, dy2 = 0.f, area_d = 0.f;
    if (valid) {
        float4 pr = ((const float4*)priors)[p];
        float4 lc = ((const float4*)arm_loc)[(size_t)b * PP + p];
        decode4(pr, lc, dx1, dy1, dx2, dy2, area_d);
    }

    #pragma unroll 6
    for (int o = 0; o < OO; o++) {
        float I = 0.f, D = 1.f;
        if (valid) {
            float4 t = s_gt[o];
            float lx = fmaxf(t.x, dx1), ly = fmaxf(t.y, dy1);
            float rx = fminf(t.z, dx2), ry = fminf(t.w, dy2);
            float iw = fmaxf(rx - lx, 0.f), ih = fmaxf(ry - ly, 0.f);
            I = iw * ih;
            D = s_at[o] + area_d - I;
        }
        s_I[w][lane][o] = I;
        s_D[w][lane][o] = D;
    }
    __syncwarp();

    if (lane < OO) {
        float wI = s_I[w][0][lane], wD = s_D[w][0][lane]; int wj = 0;
        #pragma unroll 8
        for (int j = 1; j < 32; j++) {
            float I = s_I[w][j][lane], D = s_D[w][j][lane];
            if (I * wD > wI * D) { wI = I; wD = D; wj = j; }
        }
        if (wI > 0.f) {
            float iou = wI / wD;
            unsigned pw = (unsigned)(blockIdx.x * 128 + w * 32 + wj);
            unsigned long long cand =
                (((unsigned long long)__float_as_uint(iou)) << 32) |
                (unsigned long long)(0xFFFFFFFFu - pw);
            atomicMax(&g_best_prior[b * OO + lane], cand);
        }
    }
}

// ---------------- kernel B (main stream): CE + per-row match + positive losses ----------
__global__ void __launch_bounds__(256)
k_main(const float* __restrict__ arm_loc,
       const float* __restrict__ arm_conf,
       const float* __restrict__ odm_loc,
       const float* __restrict__ odm_conf,
       const float* __restrict__ priors,
       const float* __restrict__ gt_boxes,
       const int*   __restrict__ gt_labels) {
    extern __shared__ float sh[];            // 8 warps * 4 slots * 648 floats = 82944 B
    __shared__ float4 s_gt[OO];
    __shared__ float  s_at[OO];
    __shared__ int    s_lab[OO];

    int b = blockIdx.y;
    int tid = threadIdx.x;
    int w = tid >> 5, lane = tid & 31;
    int warpg = blockIdx.x * 8 + w;          // 0..407
    int row0 = warpg * (WCH * WNC);
    size_t bbase = (size_t)b * PP;
    const float* confb = odm_conf + bbase * CC;
    float* ws = sh + w * (4 * CHF);

    #pragma unroll
    for (int c = 0; c < 3; c++) {
        const float4* src = (const float4*)(confb + (size_t)(row0 + c * WCH) * CC);
        float* dst = ws + c * CHF;
        #pragma unroll
        for (int t = 0; t < 6; t++) {
            int i = lane + t * 32;
            if (i < CHF4) cp16(dst + i * 4, src + i);
        }
        asm volatile("cp.async.commit_group;\n" ::);
    }

    if (tid < OO) {
        float4 t = ((const float4*)gt_boxes)[b * OO + tid];
        s_gt[tid] = t;
        s_at[tid] = (t.z - t.x) * (t.w - t.y);
        s_lab[tid] = gt_labels[b * OO + tid];
    }
    __syncthreads();                          // only block barrier

    int r = lane >> 2, q = lane & 3;          // 8 rows x 4 lanes per row

    #pragma unroll
    for (int c = 0; c < WNC; c++) {
        if (c + 3 < WNC) {
            const float4* src = (const float4*)(confb + (size_t)(row0 + (c + 3) * WCH) * CC);
            float* dst = ws + ((c + 3) & 3) * CHF;
            #pragma unroll
            for (int t = 0; t < 6; t++) {
                int i = lane + t * 32;
                if (i < CHF4) cp16(dst + i * 4, src + i);
            }
            asm volatile("cp.async.commit_group;\n" ::);
        }

        int p0 = row0 + c * WCH;
        int prow = p0 + r;
        size_t idx = bbase + prow;

        float4 pr = ((const float4*)priors)[prow];
        float4 al = ((const float4*)arm_loc)[idx];
        float dx1, dy1, dx2, dy2, area_d;
        decode4(pr, al, dx1, dy1, dx2, dy2, area_d);
        float bI, bD; int bo;
        best6(s_gt, s_at, q, dx1, dy1, dx2, dy2, area_d, bI, bD, bo);
        #pragma unroll
        for (int s = 1; s <= 2; s <<= 1) {
            float oI = __shfl_xor_sync(0xFFFFFFFFu, bI, s);
            float oD = __shfl_xor_sync(0xFFFFFFFFu, bD, s);
            int  obo = __shfl_xor_sync(0xFFFFFFFFu, bo, s);
            float L = oI * bD, R = bI * oD;
            if (L > R || (L == R && obo < bo)) { bI = oI; bD = oD; bo = obo; }
        }
        bool flag = (2.f * bI >= bD);

        if (c < 2)       asm volatile("cp.async.wait_group 3;\n" ::);
        else if (c == 2) asm volatile("cp.async.wait_group 2;\n" ::);
        else if (c == 3) asm volatile("cp.async.wait_group 1;\n" ::);
        else             asm volatile("cp.async.wait_group 0;\n" ::);
        __syncwarp();

        const float* s = ws + (c & 3) * CHF;
        const float* rp = s + r * CC + q * 20;
        float a0 = 0.f, a1 = 0.f;
        #pragma unroll
        for (int j = 0; j < 20; j += 2) {
            a0 += __expf(rp[j]);
            a1 += __expf(rp[j + 1]);
        }
        float e = a0 + a1;
        if (q == 0) e += __expf(s[r * CC + 80]);
        e += __shfl_xor_sync(0xFFFFFFFFu, e, 1);
        e += __shfl_xor_sync(0xFFFFFFFFu, e, 2);

        if (q == 0) {
            float lse = __logf(e);
            int conf_t = flag ? s_lab[bo] : 0;
            float ce = lse - s[r * CC + conf_t];

            float2 ac = ((const float2*)arm_conf)[idx];
            bool pos = (conf_t > 0) && ((ac.y - ac.x) > THLOG);

            g_ce_mine[idx] = pos ? 0.f : ce;

            if (pos) {
                float4 ol = ((const float4*)odm_loc)[idx];
                float sl = pos_loss(pr, al, s_gt[bo], ol);
                atomicAdd(&g_loss_l, (double)sl);
                atomicAdd(&g_loss_c, (double)ce);
                atomicAdd(&g_pos_count[b], 1);
            }
        }
        __syncwarp();
    }
}

// ---------------- kernel C: forced-positive fixup (after A and B) ----------------
__global__ void __launch_bounds__(32)
k_fix(const float* __restrict__ arm_loc,
      const float* __restrict__ arm_conf,
      const float* __restrict__ odm_loc,
      const float* __restrict__ odm_conf,
      const float* __restrict__ priors,
      const float* __restrict__ gt_boxes,
      const int*   __restrict__ gt_labels) {
    int b = blockIdx.x;
    int o = threadIdx.x;

    int p;
    if (o < OO) {
        unsigned long long fc = g_best_prior[b * OO + o];
        p = (fc >> 32) ? (int)(0xFFFFFFFFu - (unsigned)(fc & 0xFFFFFFFFu)) : 0;
    } else {
        p = 0x40000000 + o;
    }
    unsigned mm = __match_any_sync(0xFFFFFFFFu, p);
    bool winner = (o < OO) && ((31 - __clz((int)mm)) == o);
    if (!winner) return;

    size_t idx = (size_t)b * PP + p;
    const float* row = odm_conf + idx * CC;

    float eq[4];
    #pragma unroll
    for (int qq = 0; qq < 4; qq++) {
        float a0 = 0.f, a1 = 0.f;
        #pragma unroll
        for (int j = 0; j < 20; j += 2) {
            a0 += __expf(row[qq * 20 + j]);
            a1 += __expf(row[qq * 20 + j + 1]);
        }
        eq[qq] = a0 + a1;
    }
    eq[0] += __expf(row[80]);
    float lse = __logf((eq[0] + eq[1]) + (eq[2] + eq[3]));

    float4 pr = ((const float4*)priors)[p];
    float4 al = ((const float4*)arm_loc)[idx];
    float dx1, dy1, dx2, dy2, area_d;
    decode4(pr, al, dx1, dy1, dx2, dy2, area_d);
    float4 gtl[OO]; float atl[OO];
    for (int o2 = 0; o2 < OO; o2++) {
        gtl[o2] = ((const float4*)gt_boxes)[b * OO + o2];
        atl[o2] = (gtl[o2].z - gtl[o2].x) * (gtl[o2].w - gtl[o2].y);
    }
    float qI[4], qD[4]; int qO[4];
    #pragma unroll
    for (int qq = 0; qq < 4; qq++)
        best6(gtl, atl, qq, dx1, dy1, dx2, dy2, area_d, qI[qq], qD[qq], qO[qq]);
    #pragma unroll
    for (int s = 1; s <= 2; s <<= 1) {
        #pragma unroll
        for (int qq = 0; qq < 4; qq++) {
            int pp = qq ^ s;
            if (pp > qq) {
                float L1 = qI[pp] * qD[qq], R1 = qI[qq] * qD[pp];
                float nI, nD; int nO;
                if (L1 > R1 || (L1 == R1 && qO[pp] < qO[qq]))
                     { nI = qI[pp]; nD = qD[pp]; nO = qO[pp]; }
                else { nI = qI[qq]; nD = qD[qq]; nO = qO[qq]; }
                qI[qq] = nI; qD[qq] = nD; qO[qq] = nO;
                qI[pp] = nI; qD[pp] = nD; qO[pp] = nO;
            }
        }
    }
    float bI = qI[0], bD = qD[0]; int bo = qO[0];
    bool flag = (2.f * bI >= bD);

    int conf_t_old = flag ? gt_labels[b * OO + bo] : 0;
    float ce_old = lse - row[conf_t_old];
    float2 ac = ((const float2*)arm_conf)[idx];
    bool score_ok = (ac.y - ac.x) > THLOG;
    bool pos_old = (conf_t_old > 0) && score_ok;

    int conf_t_new = gt_labels[b * OO + o];
    float ce_new = lse - row[conf_t_new];
    bool pos_new = score_ok;

    g_ce_mine[idx] = pos_new ? 0.f : ce_new;

    double dLc = 0.0, dLl = 0.0; int dN = 0;
    if (pos_old || pos_new) {
        float4 ol = ((const float4*)odm_loc)[idx];
        if (pos_old) {
            dLc -= (double)ce_old; dN -= 1;
            dLl -= (double)pos_loss(pr, al, gtl[bo], ol);
        }
        if (pos_new) {
            dLc += (double)ce_new; dN += 1;
            dLl += (double)pos_loss(pr, al, gtl[o], ol);
        }
    }
    if (dLc != 0.0) atomicAdd(&g_loss_c, dLc);
    if (dLl != 0.0) atomicAdd(&g_loss_l, dLl);
    if (dN)         atomicAdd(&g_pos_count[b], dN);
}

// ---------------- kernel D: top-k via count-histogram prune + finalize ----------------
// dyn smem: PP uint list (65280) + NBIN int counts (16384)
__global__ void __launch_bounds__(1024) k_topk(float* __restrict__ out) {
    int b = blockIdx.x;
    extern __shared__ char dsm[];
    unsigned* s_list = (unsigned*)dsm;                     // [PP]
    int*      s_bcnt = (int*)(dsm + PP * 4);               // [NBIN]

    __shared__ int s_wc[32];
    __shared__ double s_wsum[32];
    __shared__ int s_B, s_ca, s_rem, s_last;
    __shared__ unsigned s_pref;

    int t = threadIdx.x;
    int warp = t >> 5, lane = t & 31;

    if (t < OO) g_best_prior[b * OO + t] = 0x00000000FFFFFFFFull;  // next replay

    #pragma unroll
    for (int i = 0; i < NBIN / 1024; i++)
        s_bcnt[t + i * 1024] = 0;
    __syncthreads();

    int np = g_pos_count[b];
    int k = 3 * np; if (k > PP - 1) k = PP - 1;

    if (k > 0) {
        // ---- pass 1: copy to smem + warp-aggregated COUNT histogram ----
        for (int i = t; i < 16384; i += 1024) {            // uniform trips
            bool valid = (i < PP);
            unsigned v = 0;
            if (valid) {
                v = __float_as_uint(g_ce_mine[(size_t)b * PP + i]);
                s_list[i] = v;
            }
            unsigned bin = v >> 19;
            unsigned act = __ballot_sync(0xFFFFFFFFu, valid);
            if (valid) {
                unsigned same = __match_any_sync(act, bin);
                if ((__ffs(same) - 1) == lane)
                    atomicAdd(&s_bcnt[bin], __popc(same));
            }
        }
        __syncthreads();

        // ---- suffix scan (counts only) to find crossing bin B ----
        int pc = 0;
        #pragma unroll
        for (int j = 0; j < 4; j++) pc += s_bcnt[t * 4 + j];
        int sc = pc;
        #pragma unroll
        for (int sh = 1; sh < 32; sh <<= 1) {
            int oc = __shfl_down_sync(0xFFFFFFFFu, sc, sh);
            if (lane + sh < 32) sc += oc;
        }
        if (lane == 0) s_wc[warp] = sc;
        __syncthreads();
        int aw = 0;
        for (int w2 = warp + 1; w2 < 32; w2++) aw += s_wc[w2];
        int above = aw + (sc - pc);                        // strictly-above count
        {
            int run = above;
            #pragma unroll
            for (int j = 3; j >= 0; j--) {
                int bin = t * 4 + j;
                int c = s_bcnt[bin];
                if (run < k && k <= run + c) { s_B = bin; s_ca = run; }
                run += c;
            }
        }
        __syncthreads();
        int B = s_B;
        int rem = k - s_ca;                                // rank within bin B
        unsigned pref = (unsigned)B << 19;

        // ---- byte-radix select of remaining 19 bits (3 filtered scans) ----
        // fixshift per pass: ALL bits >= fixshift are pinned (coarse bin + chosen bytes)
        #pragma unroll
        for (int pass = 0; pass < 3; pass++) {
            int d       = (pass == 0) ? 16 : (pass == 1) ? 8 : 0;
            int fixs    = (pass == 0) ? 19 : (pass == 1) ? 16 : 8;
            if (t < 256) s_bcnt[t] = 0;
            __syncthreads();
            unsigned want = pref >> fixs;
            for (int i = t; i < 16384; i += 1024) {
                bool part = false; unsigned bin = 0;
                if (i < PP) {
                    unsigned v = s_list[i];
                    part = ((v >> fixs) == want);
                    bin = (v >> d) & 0xFFu;
                }
                unsigned act = __ballot_sync(0xFFFFFFFFu, part);
                if (part) {
                    unsigned same = __match_any_sync(act, bin);
                    if ((__ffs(same) - 1) == lane)
                        atomicAdd(&s_bcnt[bin], __popc(same));
                }
            }
            __syncthreads();
            if (t < 32) {
                int loc[8]; int s8 = 0;
                #pragma unroll
                for (int j = 0; j < 8; j++) { loc[j] = s_bcnt[t * 8 + j]; s8 += loc[j]; }
                int suf = s8;
                #pragma unroll
                for (int sh = 1; sh < 32; sh <<= 1) {
                    int oo = __shfl_down_sync(0xFFFFFFFFu, suf, sh);
                    if (t + sh < 32) suf += oo;
                }
                int abv = suf - s8;
                int cand = -1, candgt = 0;
                int run = abv;
                #pragma unroll
                for (int j = 7; j >= 0; j--) {
                    int gt = run;
                    run += loc[j];
                    if (cand < 0 && run >= rem) { cand = t * 8 + j; candgt = gt; }
                }
                int wm = __reduce_max_sync(0xFFFFFFFFu, (unsigned)(cand + 1)) - 1;
                if (cand == wm && cand >= 0) {
                    s_rem = rem - candgt;
                    s_pref = (pref & (0xFFFFFFFFu << fixs)) | ((unsigned)cand << d);
                }
            }
            __syncthreads();
            rem = s_rem;
            pref = s_pref;
            __syncthreads();
        }
        unsigned lo = pref;                                // k-th largest value bits

        // ---- final pass: strictly-greater sum over the whole list (no atomics) ----
        double sum = 0.0; int cgt = 0;
        for (int i = t; i < PP; i += 1024) {
            unsigned v = s_list[i];
            if (v > lo) { sum += (double)__uint_as_float(v); cgt++; }
        }
        #pragma unroll
        for (int s = 16; s > 0; s >>= 1) {
            sum += __shfl_xor_sync(0xFFFFFFFFu, sum, s);
            cgt += __shfl_xor_sync(0xFFFFFFFFu, cgt, s);
        }
        if (lane == 0) { s_wsum[warp] = sum; s_wc[warp] = cgt; }
        __syncthreads();
        if (t == 0) {
            double S = 0.0; int C = 0;
            for (int w2 = 0; w2 < 32; w2++) { S += s_wsum[w2]; C += s_wc[w2]; }
            S += (double)(k - C) * (double)__uint_as_float(lo);
            atomicAdd(&g_loss_c, S);
        }
    }

    // ---- arrival + finalize by last block ----
    __threadfence();
    if (t == 0) s_last = (atomicAdd(&g_done, 1) == BB - 1);
    __syncthreads();
    if (s_last) {
        int* ib = (int*)s_list;
        if (t < BB) { ib[t] = g_pos_count[t]; g_pos_count[t] = 0; }
        __syncthreads();
        if (t == 0) {
            int N = 0;
            for (int i = 0; i < BB; i++) N += ib[i];
            double lc = atomicAdd(&g_loss_c, 0.0);
            double ll = g_loss_l;
            out[0] = (float)(ll / (double)N);
            out[1] = (float)(lc / (double)N);
            g_loss_l = 0.0; g_loss_c = 0.0; g_done = 0;
        }
    }
}

// ---------------- launch: fork k_match onto a side stream ----------------
extern "C" void kernel_launch(void* const* d_in, const int* in_sizes, int n_in,
                              void* d_out, int out_size) {
    const float* arm_loc  = (const float*)d_in[0];
    const float* arm_conf = (const float*)d_in[1];
    const float* odm_loc  = (const float*)d_in[2];
    const float* odm_conf = (const float*)d_in[3];
    const float* priors   = (const float*)d_in[4];
    const float* gt_boxes = (const float*)d_in[5];
    const int*   gt_labels= (const int*)  d_in[6];
    float* out = (float*)d_out;

    int kmain_smem = 8 * 4 * CHF * (int)sizeof(float);       // 82944 B
    int ktopk_smem = PP * 4 + NBIN * 4;                      // 81664 B

    static cudaStream_t s2 = nullptr;
    static cudaEvent_t ev1 = nullptr, ev2 = nullptr;
    static bool inited = false;
    if (!inited) {
        cudaStreamCreateWithFlags(&s2, cudaStreamNonBlocking);
        cudaEventCreateWithFlags(&ev1, cudaEventDisableTiming);
        cudaEventCreateWithFlags(&ev2, cudaEventDisableTiming);
        cudaFuncSetAttribute(k_main, cudaFuncAttributeMaxDynamicSharedMemorySize,
                             kmain_smem);
        cudaFuncSetAttribute(k_topk, cudaFuncAttributeMaxDynamicSharedMemorySize,
                             ktopk_smem);
        inited = true;
    }

    // fork: k_match on s2, concurrent with k_main on the main stream
    cudaEventRecord(ev1, 0);
    cudaStreamWaitEvent(s2, ev1, 0);
    {
        dim3 g(128, BB);
        k_match<<<g, 128, 0, s2>>>(arm_loc, priors, gt_boxes);
    }
    cudaEventRecord(ev2, s2);
    {
        dim3 g(51, BB);
        k_main<<<g, 256, kmain_smem>>>(arm_loc, arm_conf, odm_loc, odm_conf,
                                       priors, gt_boxes, gt_labels);
    }
    // join: k_fix needs both k_match (g_best_prior) and k_main (losses/ce_mine)
    cudaStreamWaitEvent(0, ev2, 0);
    k_fix<<<BB, 32>>>(arm_loc, arm_conf, odm_loc, odm_conf,
                      priors, gt_boxes, gt_labels);
    k_topk<<<BB, 1024, ktopk_smem>>>(out);
}